// round 2
// baseline (speedup 1.0000x reference)
#include <cuda_runtime.h>
#include <stdint.h>

// ---------------- problem constants ----------------
// SPARSE_SHAPE (468,468,1), WINDOW (12,12,1), BATCH 4
// _NX=_NY=40, _NZ=2 ; win_z==0 always ; full_win = 2*compact
// compact win id = b*1600 + wx*40 + wy  in [0, 6400)
#define NWc     6400
#define CH      2048
#define NB_MAX  160
#define MAXN    301056          // NB_MAX-safe bound (147*2048 covers 300000)
#define FULLM   0xFFFFFFFFu

// ---------------- static scratch (no allocations allowed) ----------------
__device__ int           g_H[NB_MAX * NWc];   // per-chunk window histograms / prefix offsets
__device__ int           g_winc0[MAXN];
__device__ int           g_winc1[MAXN];
__device__ int           g_inner0[MAXN];
__device__ int           g_inner1[MAXN];
__device__ unsigned char g_keep0[MAXN];
__device__ unsigned char g_keepF[MAXN];
__device__ int           g_counts0[NWc];
__device__ int           g_counts1[NWc];

__device__ __forceinline__ void lvl_target(int n, int& lvl, int& target) {
    if (n < 16)      { lvl = 0; target = 16; }
    else if (n < 32) { lvl = 1; target = 32; }
    else if (n < 64) { lvl = 2; target = 64; }
    else             { lvl = 3; target = 144; }
}

// ---------------- phase 0: zero histogram scratch ----------------
__global__ void k_zeroH(int total) {
    for (int i = blockIdx.x * blockDim.x + threadIdx.x; i < total; i += gridDim.x * blockDim.x)
        g_H[i] = 0;
}

// ---------------- phase 1a: compute window ids + chunk histogram (round 0) ----------------
__global__ void k_hist0(const int* __restrict__ coords, int N) {
    int c = blockIdx.x;
    int base = c * CH;
    for (int t = threadIdx.x; t < CH; t += blockDim.x) {
        int idx = base + t;
        if (idx < N) {
            int4 cc = ((const int4*)coords)[idx];        // (b,z,y,x)
            int b = cc.x, y = cc.z, x = cc.w;
            int w0 = b * 1600 + ((x + 12) / 12) * 40 + ((y + 12) / 12);
            int w1 = b * 1600 + ((x + 6)  / 12) * 40 + ((y + 6)  / 12);
            g_winc0[idx] = w0;
            g_winc1[idx] = w1;
            atomicAdd(&g_H[c * NWc + w0], 1);
        }
    }
}

// ---------------- phase 1b: chunk histogram round 1 (masked by keep0) ----------------
__global__ void k_hist1(int N) {
    int c = blockIdx.x;
    int base = c * CH;
    for (int t = threadIdx.x; t < CH; t += blockDim.x) {
        int idx = base + t;
        if (idx < N && g_keep0[idx]) {
            atomicAdd(&g_H[c * NWc + g_winc1[idx]], 1);
        }
    }
}

// ---------------- phase 2: per-window exclusive scan over chunks ----------------
__global__ void k_scan(int* __restrict__ counts, int NB) {
    int w = blockIdx.x * blockDim.x + threadIdx.x;
    if (w >= NWc) return;
    int run = 0;
#pragma unroll 4
    for (int c = 0; c < NB; c++) {
        int* p = &g_H[c * NWc + w];
        int h = *p;
        *p = run;       // exclusive prefix: base offset for chunk c
        run += h;
    }
    counts[w] = run;
}

// ---------------- phase 3: stable rank assignment (one warp per chunk) ----------------
__global__ void __launch_bounds__(32)
k_rank(const int* __restrict__ winc, const unsigned char* __restrict__ keepIn,
       const int* __restrict__ counts,
       int* __restrict__ innerOut, unsigned char* __restrict__ keepOut, int N) {
    __shared__ int offs[NWc];
    int c = blockIdx.x;
    int lane = threadIdx.x;

    // load this chunk's exclusive base offsets (contiguous 25.6 KB)
    const int4* Hv = (const int4*)&g_H[c * NWc];
#pragma unroll 8
    for (int t = lane; t < NWc / 4; t += 32)
        ((int4*)offs)[t] = Hv[t];
    __syncwarp();

    unsigned ltmask = (1u << lane) - 1u;
    int base0 = c * CH;
    for (int t = 0; t < CH; t += 32) {
        int idx = base0 + t + lane;
        bool act = idx < N;
        int w = 0; bool k = false;
        if (act) {
            w = winc[idx];
            k = keepIn ? (keepIn[idx] != 0) : true;
        }
        unsigned kmask = __ballot_sync(FULLM, k);
        unsigned peers = __match_any_sync(FULLM, w) & kmask;
        int leader = __ffs((int)peers) - 1;   // -1 if not kept
        int base = 0;
        if (k && lane == leader) {            // one leader per distinct window in this wave
            base = offs[w];
            offs[w] = base + __popc(peers);
        }
        __syncwarp();
        base = __shfl_sync(FULLM, base, leader < 0 ? 0 : leader);
        if (act) {
            int inner = k ? (base + __popc(peers & ltmask)) : -1;
            innerOut[idx] = inner;
            bool kn = false;
            if (k) {
                int lvl, target;
                lvl_target(counts[w], lvl, target);
                kn = inner < target;
            }
            keepOut[idx] = kn ? 1 : 0;
        }
        __syncwarp();                         // order offs updates across waves
    }
}

// ---------------- phase 4a: scalar output vectors ----------------
__global__ void k_outvec(float* __restrict__ out, int N,
                         size_t off_keep, size_t off_w0, size_t off_w1,
                         size_t off_dl0, size_t off_dl1,
                         size_t off_i0, size_t off_i1) {
    for (int i = blockIdx.x * blockDim.x + threadIdx.x; i < N; i += gridDim.x * blockDim.x) {
        int w0 = g_winc0[i], w1 = g_winc1[i];
        out[off_keep + i] = g_keepF[i] ? 1.0f : 0.0f;
        out[off_w0 + i]   = (float)(2 * w0);
        out[off_w1 + i]   = (float)(2 * w1);
        int l0, t0; lvl_target(g_counts0[w0], l0, t0);
        out[off_dl0 + i] = (float)l0;
        float dl1 = -1.0f;
        if (g_keep0[i]) {
            int l1, t1; lvl_target(g_counts1[w1], l1, t1);
            dl1 = (float)l1;
        }
        out[off_dl1 + i] = dl1;
        out[off_i0 + i] = (float)g_inner0[i];
        out[off_i1 + i] = (float)g_inner1[i];
    }
}

// ---------------- phase 4b: masked features + positional embeddings ----------------
// thread t = feature channel; per-thread frequency precomputed once.
__global__ void __launch_bounds__(128)
k_outfeat(const float* __restrict__ feat, const int* __restrict__ coords,
          float* __restrict__ out, int N, int C,
          size_t off_pe0, size_t off_pe1) {
    int cidx = threadIdx.x;           // 0..C-1 (C=128)
    int half = C >> 1;                // 64
    bool isy = cidx >= half;
    int j = (isy ? (cidx - half) : cidx) >> 1;        // freq index 0..31
    bool iscos = (cidx & 1);
    // 1/inv_freq = 10000^(-(2j)/(C/2)) = 2^(-j * 4*log2(1e4)/C)
    float rec = exp2f(-(float)j * (13.28771237954944987f * 4.0f / (float)C));

    for (int i = blockIdx.x; i < N; i += gridDim.x) {
        int x = __ldg(&coords[i * 4 + 3]);
        int y = __ldg(&coords[i * 4 + 2]);
        float kf = g_keepF[i] ? 1.0f : 0.0f;
        size_t row = (size_t)i * C + cidx;
        out[row] = feat[row] * kf;

        int v = isy ? y : x;
        float v0 = (float)(v % 12) - 6.0f;            // unshifted in-window coord - w/2
        float v1 = (float)((v + 6) % 12) - 6.0f;      // shifted
        float a0 = v0 * rec, a1 = v1 * rec;
        out[off_pe0 + row] = iscos ? __cosf(a0) : __sinf(a0);
        out[off_pe1 + row] = iscos ? __cosf(a1) : __sinf(a1);
    }
}

// ---------------- launch ----------------
extern "C" void kernel_launch(void* const* d_in, const int* in_sizes, int n_in,
                              void* d_out, int out_size) {
    const float* feat   = (const float*)d_in[0];
    const int*   coords = (const int*)d_in[1];
    int N = in_sizes[1] / 4;
    int C = in_sizes[0] / N;          // 128
    if (N > MAXN) N = MAXN;           // safety (setup gives exactly 300000)
    int NB = (N + CH - 1) / CH;       // 147

    float* out = (float*)d_out;
    size_t Ns = (size_t)N, Cs = (size_t)C;
    size_t off = Ns * Cs;             // feat at 0
    size_t off_keep = off; off += Ns;
    size_t off_w0   = off; off += Ns;
    size_t off_w1   = off; off += Ns;
    size_t off_dl0  = off; off += Ns;
    size_t off_dl1  = off; off += Ns;
    size_t off_i0   = off; off += Ns;
    size_t off_i1   = off; off += Ns;
    size_t off_pe0  = off; off += Ns * Cs;
    size_t off_pe1  = off;

    int*           dH = nullptr;
    int*           dC0 = nullptr;
    int*           dC1 = nullptr;
    cudaGetSymbolAddress((void**)&dH,  g_H);
    cudaGetSymbolAddress((void**)&dC0, g_counts0);
    cudaGetSymbolAddress((void**)&dC1, g_counts1);
    int*           dW0 = nullptr; cudaGetSymbolAddress((void**)&dW0, g_winc0);
    int*           dW1 = nullptr; cudaGetSymbolAddress((void**)&dW1, g_winc1);
    int*           dI0 = nullptr; cudaGetSymbolAddress((void**)&dI0, g_inner0);
    int*           dI1 = nullptr; cudaGetSymbolAddress((void**)&dI1, g_inner1);
    unsigned char* dK0 = nullptr; cudaGetSymbolAddress((void**)&dK0, g_keep0);
    unsigned char* dKF = nullptr; cudaGetSymbolAddress((void**)&dKF, g_keepF);

    int histTotal = NB * NWc;

    // ---- round 0 (unshifted windows, keep = all) ----
    k_zeroH<<<512, 256>>>(histTotal);
    k_hist0<<<NB, 256>>>(coords, N);
    k_scan<<<(NWc + 255) / 256, 256>>>(dC0, NB);
    k_rank<<<NB, 32>>>(dW0, nullptr, dC0, dI0, dK0, N);

    // ---- round 1 (shifted windows, keep = keep0) ----
    k_zeroH<<<512, 256>>>(histTotal);
    k_hist1<<<NB, 256>>>(N);
    k_scan<<<(NWc + 255) / 256, 256>>>(dC1, NB);
    k_rank<<<NB, 32>>>(dW1, dK0, dC1, dI1, dKF, N);

    // ---- outputs ----
    k_outvec<<<512, 256>>>(out, N, off_keep, off_w0, off_w1,
                           off_dl0, off_dl1, off_i0, off_i1);
    k_outfeat<<<2368, 128>>>(feat, coords, out, N, C, off_pe0, off_pe1);
}

// round 3
// speedup vs baseline: 1.1454x; 1.1454x over previous
#include <cuda_runtime.h>
#include <stdint.h>

// ---------------- problem constants ----------------
// SPARSE_SHAPE (468,468,1), WINDOW (12,12,1), BATCH 4
// _NX=_NY=40, _NZ=2 ; win_z==0 always ; full_win = 2*compact
// compact win id = b*1600 + wx*40 + wy  in [0, 6400)
#define NWc     6400
#define CH      512
#define WAVES   16              // CH / 32
#define NB_MAX  640
#define MAXN    (NB_MAX * CH)   // 327680
#define FULLM   0xFFFFFFFFu

// ---------------- static scratch (no allocations allowed) ----------------
__device__ int           g_H[NB_MAX * NWc];   // per-chunk window histograms / prefix offsets
__device__ int           g_winc0[MAXN];
__device__ int           g_winc1[MAXN];
__device__ int           g_inner0[MAXN];
__device__ int           g_inner1[MAXN];
__device__ unsigned char g_keep0[MAXN];
__device__ unsigned char g_keepF[MAXN];
__device__ int           g_counts0[NWc];
__device__ int           g_counts1[NWc];

__device__ __forceinline__ void lvl_target(int n, int& lvl, int& target) {
    if (n < 16)      { lvl = 0; target = 16; }
    else if (n < 32) { lvl = 1; target = 32; }
    else if (n < 64) { lvl = 2; target = 64; }
    else             { lvl = 3; target = 144; }
}

// ---------------- phase 0: zero histogram scratch ----------------
__global__ void k_zeroH(int total) {
    for (int i = blockIdx.x * blockDim.x + threadIdx.x; i < total; i += gridDim.x * blockDim.x)
        g_H[i] = 0;
}

// ---------------- phase 1a: compute window ids + chunk histogram (round 0) ----------------
__global__ void k_hist0(const int* __restrict__ coords, int N) {
    int c = blockIdx.x;
    int base = c * CH;
    for (int t = threadIdx.x; t < CH; t += blockDim.x) {
        int idx = base + t;
        if (idx < N) {
            int4 cc = ((const int4*)coords)[idx];        // (b,z,y,x)
            int b = cc.x, y = cc.z, x = cc.w;
            int w0 = b * 1600 + ((x + 12) / 12) * 40 + ((y + 12) / 12);
            int w1 = b * 1600 + ((x + 6)  / 12) * 40 + ((y + 6)  / 12);
            g_winc0[idx] = w0;
            g_winc1[idx] = w1;
            atomicAdd(&g_H[c * NWc + w0], 1);
        }
    }
}

// ---------------- phase 1b: chunk histogram round 1 (masked by keep0) ----------------
__global__ void k_hist1(int N) {
    int c = blockIdx.x;
    int base = c * CH;
    for (int t = threadIdx.x; t < CH; t += blockDim.x) {
        int idx = base + t;
        if (idx < N && g_keep0[idx]) {
            atomicAdd(&g_H[c * NWc + g_winc1[idx]], 1);
        }
    }
}

// ---------------- phase 2: per-window exclusive scan over chunks ----------------
__global__ void k_scan(int* __restrict__ counts, int NB) {
    int w = blockIdx.x * blockDim.x + threadIdx.x;
    if (w >= NWc) return;
    int run = 0;
#pragma unroll 8
    for (int c = 0; c < NB; c++) {
        int* p = &g_H[c * NWc + w];
        int h = *p;
        *p = run;       // exclusive prefix: base offset for chunk c
        run += h;
    }
    counts[w] = run;
}

// ---------------- phase 3: stable rank assignment (one warp per chunk) ----------------
// All global loads (window ids, keep flags, per-window targets) are prefetched
// into registers BEFORE the serial wave loop, so the per-wave dependent chain
// is only warp intrinsics + one smem RMW. 25.6KB smem/block -> 8 blocks/SM.
__global__ void __launch_bounds__(32)
k_rank(const int* __restrict__ winc, const unsigned char* __restrict__ keepIn,
       const int* __restrict__ counts,
       int* __restrict__ innerOut, unsigned char* __restrict__ keepOut, int N) {
    __shared__ int offs[NWc];
    int c = blockIdx.x;
    int lane = threadIdx.x;

    // load this chunk's exclusive base offsets (contiguous 25.6 KB)
    const int4* Hv = (const int4*)&g_H[c * NWc];
#pragma unroll
    for (int t = lane; t < NWc / 4; t += 32)
        ((int4*)offs)[t] = Hv[t];

    int base0 = c * CH;

    // prefetch everything needed in the serial loop
    int wv[WAVES], kv[WAVES], tv[WAVES];
#pragma unroll
    for (int s = 0; s < WAVES; s++) {
        int idx = base0 + s * 32 + lane;
        int act = idx < N;
        wv[s] = act ? __ldg(&winc[idx]) : 0;
        kv[s] = act ? (keepIn ? (int)keepIn[idx] : 1) : 0;
    }
#pragma unroll
    for (int s = 0; s < WAVES; s++) {
        int cnt = kv[s] ? __ldg(&counts[wv[s]]) : 0;
        int lvl, t; lvl_target(cnt, lvl, t);
        tv[s] = t;
    }
    __syncwarp();   // offs smem visible to all lanes

    unsigned ltmask = (1u << lane) - 1u;
#pragma unroll
    for (int s = 0; s < WAVES; s++) {
        unsigned kmask = __ballot_sync(FULLM, kv[s]);
        unsigned peers = __match_any_sync(FULLM, wv[s]) & kmask;
        int leader = __ffs((int)peers) - 1;   // -1 if nobody kept with this w
        int base = 0;
        if (kv[s] && lane == leader) {        // one leader per distinct window
            base = offs[wv[s]];
            offs[wv[s]] = base + __popc(peers);
        }
        base = __shfl_sync(FULLM, base, leader < 0 ? 0 : leader);
        int idx = base0 + s * 32 + lane;
        if (idx < N) {
            int inner = kv[s] ? (base + __popc(peers & ltmask)) : -1;
            innerOut[idx] = inner;
            keepOut[idx] = (kv[s] && inner < tv[s]) ? 1 : 0;
        }
        __syncwarp();                         // order offs updates across waves
    }
}

// ---------------- phase 4a: scalar output vectors ----------------
__global__ void k_outvec(float* __restrict__ out, int N,
                         size_t off_keep, size_t off_w0, size_t off_w1,
                         size_t off_dl0, size_t off_dl1,
                         size_t off_i0, size_t off_i1) {
    for (int i = blockIdx.x * blockDim.x + threadIdx.x; i < N; i += gridDim.x * blockDim.x) {
        int w0 = g_winc0[i], w1 = g_winc1[i];
        out[off_keep + i] = g_keepF[i] ? 1.0f : 0.0f;
        out[off_w0 + i]   = (float)(2 * w0);
        out[off_w1 + i]   = (float)(2 * w1);
        int l0, t0; lvl_target(g_counts0[w0], l0, t0);
        out[off_dl0 + i] = (float)l0;
        float dl1 = -1.0f;
        if (g_keep0[i]) {
            int l1, t1; lvl_target(g_counts1[w1], l1, t1);
            dl1 = (float)l1;
        }
        out[off_dl1 + i] = dl1;
        out[off_i0 + i] = (float)g_inner0[i];
        out[off_i1 + i] = (float)g_inner1[i];
    }
}

// ---------------- phase 4b: masked features + positional embeddings ----------------
// thread t = feature channel; per-thread frequency precomputed once.
__global__ void __launch_bounds__(128)
k_outfeat(const float* __restrict__ feat, const int* __restrict__ coords,
          float* __restrict__ out, int N, int C,
          size_t off_pe0, size_t off_pe1) {
    int cidx = threadIdx.x;           // 0..C-1 (C=128)
    int half = C >> 1;                // 64
    bool isy = cidx >= half;
    int j = (isy ? (cidx - half) : cidx) >> 1;        // freq index 0..31
    bool iscos = (cidx & 1);
    // 1/inv_freq = 10000^(-(2j)/(C/2)) = 2^(-j * 4*log2(1e4)/C)
    float rec = exp2f(-(float)j * (13.28771237954944987f * 4.0f / (float)C));

    for (int i = blockIdx.x; i < N; i += gridDim.x) {
        int x = __ldg(&coords[i * 4 + 3]);
        int y = __ldg(&coords[i * 4 + 2]);
        float kf = g_keepF[i] ? 1.0f : 0.0f;
        size_t row = (size_t)i * C + cidx;
        out[row] = feat[row] * kf;

        int v = isy ? y : x;
        float v0 = (float)(v % 12) - 6.0f;            // unshifted in-window coord - w/2
        float v1 = (float)((v + 6) % 12) - 6.0f;      // shifted
        float a0 = v0 * rec, a1 = v1 * rec;
        out[off_pe0 + row] = iscos ? __cosf(a0) : __sinf(a0);
        out[off_pe1 + row] = iscos ? __cosf(a1) : __sinf(a1);
    }
}

// ---------------- launch ----------------
extern "C" void kernel_launch(void* const* d_in, const int* in_sizes, int n_in,
                              void* d_out, int out_size) {
    const float* feat   = (const float*)d_in[0];
    const int*   coords = (const int*)d_in[1];
    int N = in_sizes[1] / 4;
    int C = in_sizes[0] / N;          // 128
    if (N > MAXN) N = MAXN;           // safety (setup gives exactly 300000)
    int NB = (N + CH - 1) / CH;       // 586

    float* out = (float*)d_out;
    size_t Ns = (size_t)N, Cs = (size_t)C;
    size_t off = Ns * Cs;             // feat at 0
    size_t off_keep = off; off += Ns;
    size_t off_w0   = off; off += Ns;
    size_t off_w1   = off; off += Ns;
    size_t off_dl0  = off; off += Ns;
    size_t off_dl1  = off; off += Ns;
    size_t off_i0   = off; off += Ns;
    size_t off_i1   = off; off += Ns;
    size_t off_pe0  = off; off += Ns * Cs;
    size_t off_pe1  = off;

    int* dC0 = nullptr; cudaGetSymbolAddress((void**)&dC0, g_counts0);
    int* dC1 = nullptr; cudaGetSymbolAddress((void**)&dC1, g_counts1);
    int* dW0 = nullptr; cudaGetSymbolAddress((void**)&dW0, g_winc0);
    int* dW1 = nullptr; cudaGetSymbolAddress((void**)&dW1, g_winc1);
    int* dI0 = nullptr; cudaGetSymbolAddress((void**)&dI0, g_inner0);
    int* dI1 = nullptr; cudaGetSymbolAddress((void**)&dI1, g_inner1);
    unsigned char* dK0 = nullptr; cudaGetSymbolAddress((void**)&dK0, g_keep0);
    unsigned char* dKF = nullptr; cudaGetSymbolAddress((void**)&dKF, g_keepF);

    int histTotal = NB * NWc;

    // ---- round 0 (unshifted windows, keep = all) ----
    k_zeroH<<<512, 256>>>(histTotal);
    k_hist0<<<NB, 256>>>(coords, N);
    k_scan<<<(NWc + 255) / 256, 256>>>(dC0, NB);
    k_rank<<<NB, 32>>>(dW0, nullptr, dC0, dI0, dK0, N);

    // ---- round 1 (shifted windows, keep = keep0) ----
    k_zeroH<<<512, 256>>>(histTotal);
    k_hist1<<<NB, 256>>>(N);
    k_scan<<<(NWc + 255) / 256, 256>>>(dC1, NB);
    k_rank<<<NB, 32>>>(dW1, dK0, dC1, dI1, dKF, N);

    // ---- outputs ----
    k_outvec<<<512, 256>>>(out, N, off_keep, off_w0, off_w1,
                           off_dl0, off_dl1, off_i0, off_i1);
    k_outfeat<<<2368, 128>>>(feat, coords, out, N, C, off_pe0, off_pe1);
}